// round 7
// baseline (speedup 1.0000x reference)
#include <cuda_runtime.h>
#include <math.h>

#define EDGES 40000
#define ATOMS 2000
#define F 64
#define NLM 25
#define EF ((size_t)EDGES * F)

// ============================================================================
// Compile-time real Clebsch-Gordan table (replicates reference exactly)
// ============================================================================
namespace cgbuild {

constexpr double cfact(int n){ double r=1.0; for(int i=2;i<=n;++i) r*=(double)i; return r; }
constexpr double csqrt(double v){
  if(v<=0.0) return 0.0;
  double x = v>1.0 ? v : 1.0;
  for(int i=0;i<64;++i) x = 0.5*(x + v/x);
  return x;
}
constexpr double cabsd(double v){ return v<0.0 ? -v : v; }

constexpr double cg_complex(int l1,int m1,int l2,int m2,int l3,int m3){
  if(m3 != m1+m2) return 0.0;
  int lmin = l1>l2 ? l1-l2 : l2-l1;
  if(l3 < lmin || l3 > l1+l2) return 0.0;
  double pre = (2.0*l3+1.0)*cfact(l1+l2-l3)*cfact(l1-l2+l3)*cfact(-l1+l2+l3)/cfact(l1+l2+l3+1);
  pre = csqrt(pre*cfact(l1+m1)*cfact(l1-m1)*cfact(l2+m2)*cfact(l2-m2)*cfact(l3+m3)*cfact(l3-m3));
  double s = 0.0;
  for(int k=0;k<=l1+l2-l3;++k){
    int d2=l1-m1-k, d3=l2+m2-k, d4=l3-l2+m1+k, d5=l3-l1-m2+k;
    if(d2<0||d3<0||d4<0||d5<0) continue;
    double den = cfact(k)*cfact(l1+l2-l3-k)*cfact(d2)*cfact(d3)*cfact(d4)*cfact(d5);
    s += ((k&1) ? -1.0 : 1.0)/den;
  }
  return pre*s;
}

struct CD { double re, im; };
constexpr CD cmul(CD a, CD b){ return CD{a.re*b.re - a.im*b.im, a.re*b.im + a.im*b.re}; }

constexpr double INV_SQRT2 = 0.70710678118654752440;

struct URow { int n; int m[2]; CD c[2]; };
constexpr URow urow(int l, int a){
  URow r{};
  int m = a - l;
  double s = INV_SQRT2;
  if(m==0){ r.n=1; r.m[0]=0; r.c[0]=CD{1.0,0.0}; return r; }
  if(m>0){
    r.n=2;
    r.m[0]=m;  r.c[0]=CD{ ((m&1)? -1.0:1.0)*s, 0.0};
    r.m[1]=-m; r.c[1]=CD{ s, 0.0};
    return r;
  }
  int am = -m;
  r.n=2;
  r.m[0]=m;  r.c[0]=CD{0.0, s};
  r.m[1]=am; r.c[1]=CD{0.0, -(((am&1)? -1.0:1.0))*s};
  return r;
}

constexpr int MAXE = 4608;
struct Ent { int i1,i2,i3; float c; };
struct CGTab {
  Ent e[MAXE];
  int pstart[43];
  int pl3[42];
  int n; int npaths; bool overflow;
};

constexpr CGTab build_cg(){
  CGTab T{};
  int p = 0;
  for(int l1=0;l1<=4;++l1)
  for(int l2=0;l2<=4;++l2){
    int lmin = l1>l2 ? l1-l2 : l2-l1;
    int lcap = (l1+l2 < 4) ? (l1+l2) : 4;
    for(int l3=lmin; l3<=lcap; ++l3){
      if(((l1+l2+l3)&1) != 0) continue;
      T.pstart[p] = T.n;
      T.pl3[p] = l3;
      for(int a=0;a<2*l1+1;++a)
      for(int b=0;b<2*l2+1;++b){
        double acc[9]={0,0,0,0,0,0,0,0,0};
        URow u1 = urow(l1,a);
        URow u2 = urow(l2,b);
        for(int t1=0;t1<u1.n;++t1)
        for(int t2=0;t2<u2.n;++t2){
          int m3 = u1.m[t1]+u2.m[t2];
          if(m3 > l3 || m3 < -l3) continue;
          double cc = cg_complex(l1,u1.m[t1],l2,u2.m[t2],l3,m3);
          if(cc==0.0) continue;
          CD c12 = cmul(u1.c[t1], u2.c[t2]);
          c12.re *= cc; c12.im *= cc;
          int rows[2] = { m3, -m3 };
          int nr = (m3==0) ? 1 : 2;
          for(int rr=0;rr<nr;++rr){
            int cidx = rows[rr] + l3;
            URow u3 = urow(l3, cidx);
            for(int t3=0;t3<u3.n;++t3){
              if(u3.m[t3]==m3){
                // term = c12 * conj(u3.c[t3]); take real part
                acc[cidx] += c12.re*u3.c[t3].re + c12.im*u3.c[t3].im;
              }
            }
          }
        }
        for(int c_=0;c_<2*l3+1;++c_){
          if(cabsd(acc[c_]) > 1e-10){
            if(T.n >= MAXE){ T.overflow = true; }
            else {
              T.e[T.n].i1 = l1*l1 + a;
              T.e[T.n].i2 = l2*l2 + b;
              T.e[T.n].i3 = l3*l3 + c_;
              T.e[T.n].c  = (float)acc[c_];
              T.n++;
            }
          }
        }
      }
      ++p;
    }
  }
  T.pstart[p] = T.n;
  T.npaths = p;
  return T;
}

constexpr CGTab CG = build_cg();
static_assert(!CG.overflow, "cg table overflow");
static_assert(CG.npaths == 42, "path count must be 42");
static_assert(CG.n > 0, "cg table empty");

} // namespace cgbuild

// ============================================================================
// Scratch (device globals: sanctioned no-alloc workaround)
// ============================================================================
__device__ float g_y[NLM*(size_t)EDGES*F];
__device__ float g_u[NLM*(size_t)EDGES*F];
__device__ float g_v[NLM*(size_t)EDGES*F];
__device__ float g_t[NLM*(size_t)EDGES*F];
__device__ float g_a[(size_t)ATOMS*F];

__constant__ int DEGC[NLM] = {0,1,1,1,2,2,2,2,2,3,3,3,3,3,3,3,4,4,4,4,4,4,4,4,4};

// ============================================================================
// Kernel 1: per-atom embedding a = emb[Z] @ W_emb_t ; init d_out
// ============================================================================
__global__ void __launch_bounds__(256) k_atom_emb(
    const int* __restrict__ Z, const float* __restrict__ emb,
    const float* __restrict__ Wt, float* __restrict__ a, float* __restrict__ out)
{
  int t = blockIdx.x*256 + threadIdx.x;
  if(t >= ATOMS*F) return;
  int n = t>>6, f = t&63;
  int z = Z[n];
  const float* er = emb + (size_t)z*F;
  float s = 0.f;
  #pragma unroll
  for(int k=0;k<F;++k) s = fmaf(er[k], Wt[k*F+f], s);
  a[t] = s;
  float* orow = out + (size_t)n*NLM*F + f;
  orow[0] = s;
  #pragma unroll
  for(int lm=1;lm<NLM;++lm) orow[(size_t)lm*F] = 0.f;
}

// ============================================================================
// Kernel 2: edge features y[lm][e][f] = SH(unit)[lm] * rad[f]
// ============================================================================
__global__ void __launch_bounds__(256) k_edge_y(
    const int* __restrict__ nbr, const float* __restrict__ disp,
    const int* __restrict__ Z, const float* __restrict__ Wrad,
    float* __restrict__ y)
{
  int t = blockIdx.x*256 + threadIdx.x;
  int e = t>>6, f = t&63;
  if(e >= EDGES) return;
  int j  = nbr[2*e+1];
  int zj = Z[j];
  float dx = disp[3*e+0], dy = disp[3*e+1], dz = disp[3*e+2];
  float r = sqrtf(dx*dx + dy*dy + dz*dz + 1e-12f);
  float inv = 1.0f / r;
  float x = dx*inv, yy = dy*inv, z = dz*inv;
  float fc = 0.f;
  if(r < 5.0f) fc = 0.5f*(cosf(3.14159265358979323846f * r / 5.0f) + 1.0f);

  const float* wr = Wrad + (size_t)zj*16*F + f;
  float rad = 0.f;
  #pragma unroll
  for(int k=0;k<16;++k){
    float d = r - (float)k*(5.0f/15.0f);
    float g = expf(-10.24f*d*d)*fc;
    rad = fmaf(g, wr[(size_t)k*F], rad);
  }

  float x2=x*x, y2=yy*yy, z2=z*z;
  float sh[NLM];
  sh[0]=0.28209479177387814f;
  sh[1]=0.4886025119029199f*yy;
  sh[2]=0.4886025119029199f*z;
  sh[3]=0.4886025119029199f*x;
  sh[4]=1.0925484305920792f*x*yy;
  sh[5]=1.0925484305920792f*yy*z;
  sh[6]=0.31539156525252005f*(3.f*z2-1.f);
  sh[7]=1.0925484305920792f*x*z;
  sh[8]=0.5462742152960396f*(x2-y2);
  sh[9]=0.5900435899266435f*yy*(3.f*x2-y2);
  sh[10]=2.890611442640554f*x*yy*z;
  sh[11]=0.4570457994644658f*yy*(5.f*z2-1.f);
  sh[12]=0.3731763325901154f*z*(5.f*z2-3.f);
  sh[13]=0.4570457994644658f*x*(5.f*z2-1.f);
  sh[14]=1.445305721320277f*z*(x2-y2);
  sh[15]=0.5900435899266435f*x*(x2-3.f*y2);
  sh[16]=2.5033429417967046f*x*yy*(x2-y2);
  sh[17]=1.7701307697799304f*yy*z*(3.f*x2-y2);
  sh[18]=0.9461746957575601f*x*yy*(7.f*z2-1.f);
  sh[19]=0.6690465435572892f*yy*z*(7.f*z2-3.f);
  sh[20]=0.10578554691520431f*(35.f*z2*z2-30.f*z2+3.f);
  sh[21]=0.6690465435572892f*x*z*(7.f*z2-3.f);
  sh[22]=0.47308734787878004f*(x2-y2)*(7.f*z2-1.f);
  sh[23]=1.7701307697799304f*x*z*(x2-3.f*y2);
  sh[24]=0.6258357354491761f*(x2*x2-6.f*x2*y2+y2*y2);

  float* ye = y + (size_t)e*F + f;
  #pragma unroll
  for(int lm=0;lm<NLM;++lm) ye[(size_t)lm*EF] = sh[lm]*rad;
}

// ============================================================================
// Kernel 3: degree-wise dense: dst[lm] = src[lm] (E x 64) @ W[deg(lm)] (64x64)
// BM=128, BN=64, K=64, 128 threads, 8x8 register tiles.
// As is XOR-swizzled (k ^= ((row>>3)&3)*8) so smem total is exactly 48KB
// with conflict-free reads (4 distinct mt per warp -> 4 distinct banks).
// ============================================================================
__global__ void __launch_bounds__(128) k_deg_dense(
    const float* __restrict__ src, const float* __restrict__ W,
    float* __restrict__ dst)
{
  __shared__ float As[128*64];   // swizzled
  __shared__ float Bs[64*64];

  const int lm = blockIdx.y;
  const int e0 = blockIdx.x * 128;
  const float* A = src + (size_t)lm*EF;
  float*       C = dst + (size_t)lm*EF;
  const float* B = W + (size_t)DEGC[lm]*F*F;
  const int tid = threadIdx.x;

  { // B: 64x64 = 1024 float4, 8 per thread
    const float4* B4 = reinterpret_cast<const float4*>(B);
    float4* Bs4 = reinterpret_cast<float4*>(Bs);
    #pragma unroll
    for(int i=0;i<8;++i) Bs4[tid + 128*i] = B4[tid + 128*i];
  }
  #pragma unroll
  for(int i=0;i<16;++i){ // A tile 128x64 = 2048 float4, 16 per thread
    int idx = tid + 128*i;
    int row = idx >> 4;
    int c4  = idx & 15;
    float4 val = make_float4(0.f,0.f,0.f,0.f);
    if(e0 + row < EDGES) val = reinterpret_cast<const float4*>(A + (size_t)(e0+row)*F)[c4];
    int xorv = ((row>>3)&3)*8;
    *reinterpret_cast<float4*>(&As[row*64 + ((c4*4) ^ xorv)]) = val;
  }
  __syncthreads();

  const int mt = tid >> 3;   // 0..15 (8 rows each)
  const int nt = tid & 7;    // 0..7  (8 cols each)
  const int myxor = (mt & 3) * 8;
  float acc[8][8];
  #pragma unroll
  for(int i=0;i<8;++i)
    #pragma unroll
    for(int j=0;j<8;++j) acc[i][j] = 0.f;

  #pragma unroll 4
  for(int k=0;k<64;++k){
    int kx = k ^ myxor;
    float a[8], b[8];
    #pragma unroll
    for(int i=0;i<8;++i) a[i] = As[(mt*8+i)*64 + kx];
    float4 b0 = *reinterpret_cast<const float4*>(&Bs[k*64 + nt*8]);
    float4 b1 = *reinterpret_cast<const float4*>(&Bs[k*64 + nt*8+4]);
    b[0]=b0.x; b[1]=b0.y; b[2]=b0.z; b[3]=b0.w;
    b[4]=b1.x; b[5]=b1.y; b[6]=b1.z; b[7]=b1.w;
    #pragma unroll
    for(int i=0;i<8;++i)
      #pragma unroll
      for(int j=0;j<8;++j)
        acc[i][j] = fmaf(a[i], b[j], acc[i][j]);
  }

  #pragma unroll
  for(int i=0;i<8;++i){
    int row = e0 + mt*8 + i;
    if(row < EDGES){
      float4 v0 = make_float4(acc[i][0],acc[i][1],acc[i][2],acc[i][3]);
      float4 v1 = make_float4(acc[i][4],acc[i][5],acc[i][6],acc[i][7]);
      float4* crow = reinterpret_cast<float4*>(C + (size_t)row*F + nt*8);
      crow[0] = v0; crow[1] = v1;
    }
  }
}

// ============================================================================
// Kernel 4: CG tensor product, template-unrolled with literal indices.
// ============================================================================
template<int Lo, int Hi, int L3SQ>
__device__ __forceinline__ void ent_run(const float* __restrict__ u,
                                        const float* __restrict__ v,
                                        float* __restrict__ praw)
{
  if constexpr (Hi - Lo == 1) {
    constexpr int i1 = cgbuild::CG.e[Lo].i1;
    constexpr int i2 = cgbuild::CG.e[Lo].i2;
    constexpr int i3 = cgbuild::CG.e[Lo].i3 - L3SQ;
    constexpr float c = cgbuild::CG.e[Lo].c;
    praw[i3] = fmaf(u[i1]*v[i2], c, praw[i3]);
  } else if constexpr (Hi > Lo) {
    constexpr int Mid = Lo + (Hi - Lo)/2;
    ent_run<Lo, Mid, L3SQ>(u, v, praw);
    ent_run<Mid, Hi, L3SQ>(u, v, praw);
  }
}

template<int P>
__device__ __forceinline__ void path_run(const float* __restrict__ u,
                                         const float* __restrict__ v,
                                         float* __restrict__ t,
                                         const float* __restrict__ wp, int f)
{
  if constexpr (P < 42) {
    constexpr int l3 = cgbuild::CG.pl3[P];
    constexpr int s  = cgbuild::CG.pstart[P];
    constexpr int e  = cgbuild::CG.pstart[P+1];
    float wpf = wp[P*64 + f];
    float praw[2*l3+1];
    #pragma unroll
    for(int c=0;c<2*l3+1;++c) praw[c] = 0.f;
    ent_run<s, e, l3*l3>(u, v, praw);
    #pragma unroll
    for(int c=0;c<2*l3+1;++c)
      t[l3*l3+c] = fmaf(praw[c], wpf, t[l3*l3+c]);
    path_run<P+1>(u, v, t, wp, f);
  }
}

__global__ void __launch_bounds__(128) k_cg(
    const float* __restrict__ u_, const float* __restrict__ v_,
    const float* __restrict__ wp, float* __restrict__ t_)
{
  int t = blockIdx.x*128 + threadIdx.x;
  if(t >= EDGES*F) return;
  int f = t & 63;

  float u[NLM], v[NLM], tacc[NLM];
  #pragma unroll
  for(int lm=0;lm<NLM;++lm){
    u[lm] = u_[(size_t)lm*EF + t];
    v[lm] = v_[(size_t)lm*EF + t];
    tacc[lm] = 0.f;
  }

  path_run<0>(u, v, tacc, wp, f);

  #pragma unroll
  for(int lm=0;lm<NLM;++lm) t_[(size_t)lm*EF + t] = tacc[lm];
}

// ============================================================================
// Kernel 5: scale + scatter-add to atoms
// ============================================================================
__global__ void __launch_bounds__(256) k_scatter(
    const float* __restrict__ y, const float* __restrict__ a,
    const int* __restrict__ nbr, const float* __restrict__ twt,
    float* __restrict__ out)
{
  int t = blockIdx.x*256 + threadIdx.x;
  int e = t>>6, f = t&63;
  if(e >= EDGES) return;
  int i = nbr[2*e];
  float af = a[(size_t)i*F + f];
  float* orow = out + (size_t)i*NLM*F + f;
  #pragma unroll
  for(int lm=0;lm<NLM;++lm){
    float val = y[(size_t)lm*EF + t] * af * twt[DEGC[lm]*F + f];
    atomicAdd(&orow[(size_t)lm*F], val);
  }
}

// ============================================================================
// Launch
// ============================================================================
extern "C" void kernel_launch(void* const* d_in, const int* in_sizes, int n_in,
                              void* d_out, int out_size)
{
  const int*   Z     = (const int*)  d_in[0];
  const int*   nbr   = (const int*)  d_in[1];
  const float* disp  = (const float*)d_in[2];
  const float* emb   = (const float*)d_in[3];
  const float* Wembt = (const float*)d_in[4];
  const float* Wrad  = (const float*)d_in[5];
  const float* W1[2] = { (const float*)d_in[6],  (const float*)d_in[10] };
  const float* W2[2] = { (const float*)d_in[7],  (const float*)d_in[11] };
  const float* wp[2] = { (const float*)d_in[8],  (const float*)d_in[12] };
  const float* Wo[2] = { (const float*)d_in[9],  (const float*)d_in[13] };
  const float* twt   = (const float*)d_in[14];
  float* out = (float*)d_out;

  float *y, *u, *v, *t, *a;
  cudaGetSymbolAddress((void**)&y, g_y);
  cudaGetSymbolAddress((void**)&u, g_u);
  cudaGetSymbolAddress((void**)&v, g_v);
  cudaGetSymbolAddress((void**)&t, g_t);
  cudaGetSymbolAddress((void**)&a, g_a);

  k_atom_emb<<<(ATOMS*F + 255)/256, 256>>>(Z, emb, Wembt, a, out);
  k_edge_y<<<(EDGES*F + 255)/256, 256>>>(nbr, disp, Z, Wrad, y);

  dim3 gg((EDGES + 127)/128, NLM);
  for(int L=0; L<2; ++L){
    k_deg_dense<<<gg, 128>>>(y, W1[L], u);
    k_deg_dense<<<gg, 128>>>(y, W2[L], v);
    k_cg<<<(EDGES*F + 127)/128, 128>>>(u, v, wp[L], t);
    k_deg_dense<<<gg, 128>>>(t, Wo[L], y);
  }

  k_scatter<<<(EDGES*F + 255)/256, 256>>>(y, a, nbr, twt, out);
}